// round 16
// baseline (speedup 1.0000x reference)
#include <cuda_runtime.h>
#include <stdint.h>

#define BB 16
#define NN 2048
#define KK 20
#define ROWS (BB * NN)
#define LSTRIDE 512          // adjacency entries per row (20 direct + transpose)
#define TCAP (LSTRIDE - KK)
#define CAP 256              // smem candidate capacity == blockDim
#define TH1 2.2f
#define PREF1 2.19978f       // 2.2 - 1.1e-4 (covers rounding; noise in [0,1))
#define TH2 1.8f
#define RETRY_GRID 4096
#define WROWS 4              // rows per writer block

// ---- scratch (static __device__ — no allocations allowed) ----
__device__ unsigned long long g_list[(size_t)ROWS * LSTRIDE]; // (col<<32)|bits(v)
__device__ int g_tcnt[ROWS];    // transpose counters (zero-init; writer re-zeroes)
__device__ float g_dinv[ROWS];
__device__ int g_retry[ROWS];   // rows needing the slow exact path
__device__ int g_retry_cnt;     // zero-init; writer re-zeroes

// emit winner (col, relu value v) of `row` into slot s of the adjacency lists
__device__ __forceinline__ void emit(int row, int b, int s, int col, float v) {
    g_list[(size_t)row * LSTRIDE + s] =
        ((unsigned long long)col << 32) | (unsigned long long)__float_as_uint(v);
    int jrow = b * NN + col;
    uint32_t t = atomicAdd((unsigned int*)&g_tcnt[jrow], 1u);
    if (t < TCAP)
        g_list[(size_t)jrow * LSTRIDE + KK + t] =
            ((unsigned long long)(row & 2047) << 32)
          | (unsigned long long)__float_as_uint(v);
}

// ---------------------------------------------------------------------------
// FAST kernel: one block (256 threads) per row. Streams ONLY A (coalesced
// float4); register pre-filter a > 2.2-1.1e-4 (superset of {doped > 2.2})
// pushed straight to smem — A registers die immediately. CAP == blockDim so
// each thread owns at most one candidate: phase 2 is straight-line (one
// scattered noise load, exact key build), certification via
// __syncthreads_count (#{doped > 2.2} >= K ==> top-K lies in candidate set).
// Exact rank-count, jax lowest-index tie-break (key = doped<<11 | 2047-col),
// slot = rank. ANY failure -> append row to retry list and return.
__global__ __launch_bounds__(256) void k_topk(const float* __restrict__ A,
                                              const float* __restrict__ Noise) {
    const int row  = blockIdx.x;       // b * NN + i
    const int tid  = threadIdx.x;
    const int b    = row >> 11;
    const size_t base = (size_t)row << 11;

    __shared__ unsigned long long sP[CAP];   // (a_bits << 11) | col
    __shared__ unsigned long long sK[CAP];   // (doped_bits << 11) | (2047-col)
    __shared__ float    sV[CAP];             // relu value (= a, since a > 0)
    __shared__ uint32_t s_cnt;

    if (tid == 0) s_cnt = 0;
    __syncthreads();

    // ---- stream A, pre-filter in registers, push survivors to smem ----
    {
        const float4* a4 = (const float4*)(A + base);
        float4 av  = __ldcs(a4 + tid);
        float4 av2 = __ldcs(a4 + 256 + tid);
        float aa[8] = {av.x, av.y, av.z, av.w, av2.x, av2.y, av2.z, av2.w};
#pragma unroll
        for (int e = 0; e < 8; e++) {
            if (aa[e] > PREF1) {
                int col = (e < 4) ? (tid * 4 + e) : (1024 + tid * 4 + (e - 4));
                uint32_t p = atomicAdd(&s_cnt, 1u);
                if (p < CAP)
                    sP[p] = ((unsigned long long)__float_as_uint(aa[e]) << 11)
                          | (unsigned long long)col;
            }
        }
    }   // aa[] dead here
    __syncthreads();
    const uint32_t M = s_cnt;
    const bool sane = (M >= KK && M <= CAP);

    // ---- phase 2: one candidate per thread; certify via syncthreads_count
    bool certified = false;
    if (sane && tid < M) {
        unsigned long long e = sP[tid];
        int   col = (int)(e & 2047u);
        float a   = __uint_as_float((uint32_t)(e >> 11));
        float n   = __ldg(Noise + base + col);
        float d   = __fadd_rn(a, __fmul_rn(n, 1e-4f));
        uint32_t dbits = __float_as_uint(d);
        sK[tid] = ((unsigned long long)dbits << 11)
                | (unsigned long long)(2047 - col);
        sV[tid] = a;
        certified = (dbits > __float_as_uint(TH1));
    }
    const int ncert = __syncthreads_count(certified);
    const bool ok = sane && (ncert >= KK);

    if (!ok) {
        if (tid == 0) {
            int p = atomicAdd(&g_retry_cnt, 1);
            g_retry[p] = row;
        }
        return;
    }

    // ---- exact rank-count within certified superset; slot = rank ----
    if (tid < M) {
        const unsigned long long key = sK[tid];
        uint32_t rank = 0;
#pragma unroll 4
        for (uint32_t q = 0; q < M; q++)
            rank += (sK[q] > key);
        if (rank < KK)
            emit(row, b, (int)rank, 2047 - (int)(key & 2047u), sV[tid]);
    }
}

// ---------------------------------------------------------------------------
// SLOW exact kernel for retried rows (~5%). Fixed grid; each block strides
// over the retry list. Full coalesced A+noise reload, all 2048 keys,
// 1.8-threshold tier then accept-all; exact rank-count.
__global__ __launch_bounds__(256) void k_retry(const float* __restrict__ A,
                                               const float* __restrict__ Noise) {
    const int tid = threadIdx.x;
    const int nretry = g_retry_cnt;

    for (int ri = blockIdx.x; ri < nretry; ri += RETRY_GRID) {
        const int row = g_retry[ri];
        const int b   = row >> 11;
        const size_t base = (size_t)row << 11;

        __shared__ unsigned long long sK[NN];
        __shared__ float    sV[NN];
        __shared__ uint32_t s_cnt;
        __syncthreads();               // protect smem reuse across iterations
        if (tid == 0) s_cnt = 0;

        const float4* a4 = (const float4*)(A + base);
        const float4* n4 = (const float4*)(Noise + base);
        float4 av  = __ldg(a4 + tid);
        float4 av2 = __ldg(a4 + 256 + tid);
        float4 nv  = __ldg(n4 + tid);
        float4 nv2 = __ldg(n4 + 256 + tid);

        float    rv[8];
        uint32_t db[8];
        {
            float aa[8] = {av.x, av.y, av.z, av.w, av2.x, av2.y, av2.z, av2.w};
            float no[8] = {nv.x, nv.y, nv.z, nv.w, nv2.x, nv2.y, nv2.z, nv2.w};
#pragma unroll
            for (int e = 0; e < 8; e++) {
                rv[e] = fmaxf(aa[e], 0.0f);
                float d = __fadd_rn(rv[e], __fmul_rn(no[e], 1e-4f));
                db[e] = __float_as_uint(d);
            }
        }
        __syncthreads();

        // tier @1.8 (register test, no extra loads)
        {
            const uint32_t TH = __float_as_uint(TH2);
#pragma unroll
            for (int e = 0; e < 8; e++) {
                if (db[e] > TH) {
                    int col = (e < 4) ? (tid * 4 + e) : (1024 + tid * 4 + (e - 4));
                    uint32_t p = atomicAdd(&s_cnt, 1u);
                    sK[p] = ((unsigned long long)db[e] << 11)
                          | (unsigned long long)(2047 - col);
                    sV[p] = rv[e];
                }
            }
        }
        __syncthreads();
        uint32_t M = s_cnt;

        if (M < KK) {
            // accept-all: exact over all 2048 keys
#pragma unroll
            for (int e = 0; e < 8; e++) {
                int col = (e < 4) ? (tid * 4 + e) : (1024 + tid * 4 + (e - 4));
                sK[col] = ((unsigned long long)db[e] << 11)
                        | (unsigned long long)(2047 - col);
                sV[col] = rv[e];
            }
            __syncthreads();
            M = NN;
        }

        for (uint32_t i = tid; i < M; i += 256) {
            const unsigned long long key = sK[i];
            uint32_t rank = 0;
#pragma unroll 4
            for (uint32_t q = 0; q < M; q++)
                rank += (sK[q] > key);
            if (rank < KK)
                emit(row, b, (int)rank, 2047 - (int)(key & 2047u), sV[i]);
        }
    }
}

// ---------------------------------------------------------------------------
// Warp per row: d_i = 1 + 0.5 * sum(list values); dinv = rsqrt(d_i).
__global__ __launch_bounds__(256) void k_deg() {
    int warp = (blockIdx.x * 256 + threadIdx.x) >> 5;
    int lane = threadIdx.x & 31;
    if (warp >= ROWS) return;
    int tc = g_tcnt[warp]; if (tc > TCAP) tc = TCAP;
    int n  = KK + tc;
    float s = 0.0f;
    const unsigned long long* lst = g_list + (size_t)warp * LSTRIDE;
    for (int i = lane; i < n; i += 32)
        s += __uint_as_float((uint32_t)lst[i]);
#pragma unroll
    for (int off = 16; off; off >>= 1)
        s += __shfl_down_sync(0xffffffffu, s, off);
    if (lane == 0)
        g_dinv[warp] = rsqrtf(fmaf(0.5f, s, 1.0f));
}

// ---------------------------------------------------------------------------
// Block per FOUR rows: zero 4 smem rows, scatter weighted lists + diagonals
// (dinv via L2-hot __ldg), stream all 4 dense rows out evict-first; re-zero
// counters. Amortizes per-block latency chains over 32 KB of stores.
__global__ __launch_bounds__(256) void k_writer(float* __restrict__ out) {
    const int row0 = blockIdx.x * WROWS;   // 4 consecutive rows, same batch
    const int tid  = threadIdx.x;
    const int b    = row0 >> 11;

    __shared__ float srow[WROWS][NN];
#pragma unroll
    for (int r = 0; r < WROWS; r++) {
        float4* s4 = (float4*)srow[r];
        s4[tid]       = make_float4(0.f, 0.f, 0.f, 0.f);
        s4[256 + tid] = make_float4(0.f, 0.f, 0.f, 0.f);
    }
    __syncthreads();

#pragma unroll
    for (int r = 0; r < WROWS; r++) {
        const int row = row0 + r;
        const float di = g_dinv[row];
        int tc = g_tcnt[row]; if (tc > TCAP) tc = TCAP;
        const int n = KK + tc;
        const unsigned long long* lst = g_list + (size_t)row * LSTRIDE;
        for (int t = tid; t < n; t += 256) {
            unsigned long long e = lst[t];
            int   col = (int)(e >> 32);
            float v   = __uint_as_float((uint32_t)e);
            atomicAdd(&srow[r][col],
                      0.5f * v * di * __ldg(&g_dinv[b * NN + col]));
        }
        if (tid == (r & 255))
            atomicAdd(&srow[r][row & 2047], di * di);
    }
    __syncthreads();

    float4* o4 = (float4*)(out + ((size_t)row0 << 11));
#pragma unroll
    for (int r = 0; r < WROWS; r++) {
        float4* s4 = (float4*)srow[r];
        __stcs(&o4[r * 512 + tid],       s4[tid]);
        __stcs(&o4[r * 512 + 256 + tid], s4[256 + tid]);
    }

    if (tid < WROWS) g_tcnt[row0 + tid] = 0;  // next call sees zeroed counters
    if (blockIdx.x == 0 && tid == WROWS) g_retry_cnt = 0;
}

// ---------------------------------------------------------------------------
extern "C" void kernel_launch(void* const* d_in, const int* in_sizes, int n_in,
                              void* d_out, int out_size) {
    const float* A     = (const float*)d_in[0];
    const float* Noise = (const float*)d_in[1];
    float* out = (float*)d_out;

    k_topk <<<ROWS, 256>>>(A, Noise);
    k_retry<<<RETRY_GRID, 256>>>(A, Noise);
    k_deg  <<<(ROWS * 32 + 255) / 256, 256>>>();
    k_writer<<<ROWS / WROWS, 256>>>(out);
}

// round 17
// speedup vs baseline: 1.0678x; 1.0678x over previous
#include <cuda_runtime.h>
#include <stdint.h>

#define BB 16
#define NN 2048
#define KK 20
#define ROWS (BB * NN)
#define LSTRIDE 512          // adjacency entries per row (20 direct + transpose)
#define TCAP (LSTRIDE - KK)
#define CAP 256              // smem candidate capacity == blockDim
#define TH1 2.2f
#define PREF1 2.19978f       // 2.2 - 1.1e-4 (covers rounding; noise in [0,1))
#define TH2 1.8f
#define RETRY_GRID 4096

// ---- scratch (static __device__ — no allocations allowed) ----
__device__ unsigned long long g_list[(size_t)ROWS * LSTRIDE]; // (col<<32)|bits(v)
__device__ int g_tcnt[ROWS];    // transpose counters (zero-init; writer re-zeroes)
__device__ float g_dinv[ROWS];
__device__ int g_retry[ROWS];   // rows needing the slow exact path
__device__ int g_retry_cnt;     // zero-init; writer re-zeroes

// emit winner (col, relu value v) of `row` into slot s of the adjacency lists
__device__ __forceinline__ void emit(int row, int b, int s, int col, float v) {
    g_list[(size_t)row * LSTRIDE + s] =
        ((unsigned long long)col << 32) | (unsigned long long)__float_as_uint(v);
    int jrow = b * NN + col;
    uint32_t t = atomicAdd((unsigned int*)&g_tcnt[jrow], 1u);
    if (t < TCAP)
        g_list[(size_t)jrow * LSTRIDE + KK + t] =
            ((unsigned long long)(row & 2047) << 32)
          | (unsigned long long)__float_as_uint(v);
}

// ---------------------------------------------------------------------------
// FAST kernel: one block (256 threads) per row. Streams ONLY A (coalesced
// float4); register pre-filter a > 2.2-1.1e-4 (superset of {doped > 2.2})
// pushed straight to smem — A registers die immediately. CAP == blockDim so
// each thread owns at most one candidate: phase 2 is straight-line (one
// scattered noise load, exact key build), certification via
// __syncthreads_count (#{doped > 2.2} >= K ==> top-K lies in candidate set).
// Exact rank-count, jax lowest-index tie-break (key = doped<<11 | 2047-col),
// slot = rank. ANY failure -> append row to retry list and return.
__global__ __launch_bounds__(256) void k_topk(const float* __restrict__ A,
                                              const float* __restrict__ Noise) {
    const int row  = blockIdx.x;       // b * NN + i
    const int tid  = threadIdx.x;
    const int b    = row >> 11;
    const size_t base = (size_t)row << 11;

    __shared__ unsigned long long sP[CAP];   // (a_bits << 11) | col
    __shared__ unsigned long long sK[CAP];   // (doped_bits << 11) | (2047-col)
    __shared__ float    sV[CAP];             // relu value (= a, since a > 0)
    __shared__ uint32_t s_cnt;

    if (tid == 0) s_cnt = 0;
    __syncthreads();

    // ---- stream A, pre-filter in registers, push survivors to smem ----
    {
        const float4* a4 = (const float4*)(A + base);
        float4 av  = __ldcs(a4 + tid);
        float4 av2 = __ldcs(a4 + 256 + tid);
        float aa[8] = {av.x, av.y, av.z, av.w, av2.x, av2.y, av2.z, av2.w};
#pragma unroll
        for (int e = 0; e < 8; e++) {
            if (aa[e] > PREF1) {
                int col = (e < 4) ? (tid * 4 + e) : (1024 + tid * 4 + (e - 4));
                uint32_t p = atomicAdd(&s_cnt, 1u);
                if (p < CAP)
                    sP[p] = ((unsigned long long)__float_as_uint(aa[e]) << 11)
                          | (unsigned long long)col;
            }
        }
    }   // aa[] dead here
    __syncthreads();
    const uint32_t M = s_cnt;
    const bool sane = (M >= KK && M <= CAP);

    // ---- phase 2: one candidate per thread; certify via syncthreads_count
    bool certified = false;
    if (sane && tid < M) {
        unsigned long long e = sP[tid];
        int   col = (int)(e & 2047u);
        float a   = __uint_as_float((uint32_t)(e >> 11));
        float n   = __ldg(Noise + base + col);
        float d   = __fadd_rn(a, __fmul_rn(n, 1e-4f));
        uint32_t dbits = __float_as_uint(d);
        sK[tid] = ((unsigned long long)dbits << 11)
                | (unsigned long long)(2047 - col);
        sV[tid] = a;
        certified = (dbits > __float_as_uint(TH1));
    }
    const int ncert = __syncthreads_count(certified);
    const bool ok = sane && (ncert >= KK);

    if (!ok) {
        if (tid == 0) {
            int p = atomicAdd(&g_retry_cnt, 1);
            g_retry[p] = row;
        }
        return;
    }

    // ---- exact rank-count within certified superset; slot = rank ----
    if (tid < M) {
        const unsigned long long key = sK[tid];
        uint32_t rank = 0;
#pragma unroll 4
        for (uint32_t q = 0; q < M; q++)
            rank += (sK[q] > key);
        if (rank < KK)
            emit(row, b, (int)rank, 2047 - (int)(key & 2047u), sV[tid]);
    }
}

// ---------------------------------------------------------------------------
// SLOW exact kernel for retried rows (~5%). Fixed grid; each block strides
// over the retry list. Full coalesced A+noise reload, all 2048 keys,
// 1.8-threshold tier then accept-all; exact rank-count.
__global__ __launch_bounds__(256) void k_retry(const float* __restrict__ A,
                                               const float* __restrict__ Noise) {
    const int tid = threadIdx.x;
    const int nretry = g_retry_cnt;

    for (int ri = blockIdx.x; ri < nretry; ri += RETRY_GRID) {
        const int row = g_retry[ri];
        const int b   = row >> 11;
        const size_t base = (size_t)row << 11;

        __shared__ unsigned long long sK[NN];
        __shared__ float    sV[NN];
        __shared__ uint32_t s_cnt;
        __syncthreads();               // protect smem reuse across iterations
        if (tid == 0) s_cnt = 0;

        const float4* a4 = (const float4*)(A + base);
        const float4* n4 = (const float4*)(Noise + base);
        float4 av  = __ldg(a4 + tid);
        float4 av2 = __ldg(a4 + 256 + tid);
        float4 nv  = __ldg(n4 + tid);
        float4 nv2 = __ldg(n4 + 256 + tid);

        float    rv[8];
        uint32_t db[8];
        {
            float aa[8] = {av.x, av.y, av.z, av.w, av2.x, av2.y, av2.z, av2.w};
            float no[8] = {nv.x, nv.y, nv.z, nv.w, nv2.x, nv2.y, nv2.z, nv2.w};
#pragma unroll
            for (int e = 0; e < 8; e++) {
                rv[e] = fmaxf(aa[e], 0.0f);
                float d = __fadd_rn(rv[e], __fmul_rn(no[e], 1e-4f));
                db[e] = __float_as_uint(d);
            }
        }
        __syncthreads();

        // tier @1.8 (register test, no extra loads)
        {
            const uint32_t TH = __float_as_uint(TH2);
#pragma unroll
            for (int e = 0; e < 8; e++) {
                if (db[e] > TH) {
                    int col = (e < 4) ? (tid * 4 + e) : (1024 + tid * 4 + (e - 4));
                    uint32_t p = atomicAdd(&s_cnt, 1u);
                    sK[p] = ((unsigned long long)db[e] << 11)
                          | (unsigned long long)(2047 - col);
                    sV[p] = rv[e];
                }
            }
        }
        __syncthreads();
        uint32_t M = s_cnt;

        if (M < KK) {
            // accept-all: exact over all 2048 keys
#pragma unroll
            for (int e = 0; e < 8; e++) {
                int col = (e < 4) ? (tid * 4 + e) : (1024 + tid * 4 + (e - 4));
                sK[col] = ((unsigned long long)db[e] << 11)
                        | (unsigned long long)(2047 - col);
                sV[col] = rv[e];
            }
            __syncthreads();
            M = NN;
        }

        for (uint32_t i = tid; i < M; i += 256) {
            const unsigned long long key = sK[i];
            uint32_t rank = 0;
#pragma unroll 4
            for (uint32_t q = 0; q < M; q++)
                rank += (sK[q] > key);
            if (rank < KK)
                emit(row, b, (int)rank, 2047 - (int)(key & 2047u), sV[i]);
        }
    }
}

// ---------------------------------------------------------------------------
// Warp per row: d_i = 1 + 0.5 * sum(list values); dinv = rsqrt(d_i).
__global__ __launch_bounds__(256) void k_deg() {
    int warp = (blockIdx.x * 256 + threadIdx.x) >> 5;
    int lane = threadIdx.x & 31;
    if (warp >= ROWS) return;
    int tc = g_tcnt[warp]; if (tc > TCAP) tc = TCAP;
    int n  = KK + tc;
    float s = 0.0f;
    const unsigned long long* lst = g_list + (size_t)warp * LSTRIDE;
    for (int i = lane; i < n; i += 32)
        s += __uint_as_float((uint32_t)lst[i]);
#pragma unroll
    for (int off = 16; off; off >>= 1)
        s += __shfl_down_sync(0xffffffffu, s, off);
    if (lane == 0)
        g_dinv[warp] = rsqrtf(fmaf(0.5f, s, 1.0f));
}

// ---------------------------------------------------------------------------
// Block per TWO rows (measured best): zero 2 smem rows, scatter both weighted
// lists + diagonals (dinv via L2-hot __ldg), stream both rows out
// evict-first; re-zero counters.
__global__ __launch_bounds__(256) void k_writer(float* __restrict__ out) {
    const int row0 = blockIdx.x * 2;       // row1 = row0 + 1, same batch
    const int tid  = threadIdx.x;
    const int b    = row0 >> 11;

    __shared__ float srow[2][NN];
    float4* s40 = (float4*)srow[0];
    float4* s41 = (float4*)srow[1];
    s40[tid]       = make_float4(0.f, 0.f, 0.f, 0.f);
    s40[256 + tid] = make_float4(0.f, 0.f, 0.f, 0.f);
    s41[tid]       = make_float4(0.f, 0.f, 0.f, 0.f);
    s41[256 + tid] = make_float4(0.f, 0.f, 0.f, 0.f);

    const float di0 = g_dinv[row0];
    const float di1 = g_dinv[row0 + 1];
    int tc0 = g_tcnt[row0];     if (tc0 > TCAP) tc0 = TCAP;
    int tc1 = g_tcnt[row0 + 1]; if (tc1 > TCAP) tc1 = TCAP;
    const int n0 = KK + tc0;
    const int n1 = KK + tc1;
    __syncthreads();

    const unsigned long long* lst0 = g_list + (size_t)row0 * LSTRIDE;
    const unsigned long long* lst1 = lst0 + LSTRIDE;
    for (int t = tid; t < n0; t += 256) {
        unsigned long long e = lst0[t];
        int   col = (int)(e >> 32);
        float v   = __uint_as_float((uint32_t)e);
        atomicAdd(&srow[0][col], 0.5f * v * di0 * __ldg(&g_dinv[b * NN + col]));
    }
    for (int t = tid; t < n1; t += 256) {
        unsigned long long e = lst1[t];
        int   col = (int)(e >> 32);
        float v   = __uint_as_float((uint32_t)e);
        atomicAdd(&srow[1][col], 0.5f * v * di1 * __ldg(&g_dinv[b * NN + col]));
    }
    if (tid == 0) atomicAdd(&srow[0][row0 & 2047],       di0 * di0);
    if (tid == 1) atomicAdd(&srow[1][(row0 + 1) & 2047], di1 * di1);
    __syncthreads();

    float4* o4 = (float4*)(out + ((size_t)row0 << 11));
    __stcs(&o4[tid],       s40[tid]);
    __stcs(&o4[256 + tid], s40[256 + tid]);
    __stcs(&o4[512 + tid], s41[tid]);
    __stcs(&o4[768 + tid], s41[256 + tid]);

    if (tid == 0) g_tcnt[row0] = 0;          // next call sees zeroed counters
    if (tid == 1) g_tcnt[row0 + 1] = 0;
    if (blockIdx.x == 0 && tid == 2) g_retry_cnt = 0;
}

// ---------------------------------------------------------------------------
extern "C" void kernel_launch(void* const* d_in, const int* in_sizes, int n_in,
                              void* d_out, int out_size) {
    const float* A     = (const float*)d_in[0];
    const float* Noise = (const float*)d_in[1];
    float* out = (float*)d_out;

    k_topk <<<ROWS, 256>>>(A, Noise);
    k_retry<<<RETRY_GRID, 256>>>(A, Noise);
    k_deg  <<<(ROWS * 32 + 255) / 256, 256>>>();
    k_writer<<<ROWS / 2, 256>>>(out);
}